// round 6
// baseline (speedup 1.0000x reference)
#include <cuda_runtime.h>
#include <cuda_fp16.h>

// DDLG autoencoder, fully fused. Activations stored in SMEM as half2 packing
// TWO batch rows per 32-bit word; gate recurrences computed in half2 SIMD
// (both rows per HFMA2), epilogue mix in fp32.
// sizes: 4096 -> 2048 -> 1024 -> 2048 -> 4096, batch 4096, NUM_CONN=8.

#define BATCH 4096
#define F0 4096
#define O0 2048
#define O1 1024
#define O2 2048
#define O3 4096
#define TOTAL_O (O0 + O1 + O2 + O3)

#define RPB 8            // batch rows per block (= 4 row-pairs)
#define THREADS 768
#define NWARP (THREADS / 32)
#define S2A 4            // half2 stride per column, buffer A (16B/col)
#define S2B 5            // half2 stride per column, buffer B (20B/col, bank-spread)
#define BUFA_H2 (F0 * S2A)   // 16384 half2 = 64KB
#define BUFB_H2 (O0 * S2B)   // 10240 half2 = 40KB
#define SMEM_BYTES ((BUFA_H2 + BUFB_H2) * 4)   // 104KB -> 2 blocks/SM

// per-neuron mixing probabilities (softmax(w) or one-hot), precomputed
__device__ float g_probs[TOTAL_O * 4];

__global__ void prob_kernel(const float* __restrict__ w0, const float* __restrict__ w1,
                            const float* __restrict__ w2, const float* __restrict__ w3,
                            const int* __restrict__ is_train) {
    int t = blockIdx.x * blockDim.x + threadIdx.x;
    if (t >= TOTAL_O) return;
    const float* w;
    if (t < O0)                w = w0 + t * 4;
    else if (t < O0 + O1)      w = w1 + (t - O0) * 4;
    else if (t < O0 + O1 + O2) w = w2 + (t - O0 - O1) * 4;
    else                       w = w3 + (t - O0 - O1 - O2) * 4;
    float a = w[0], b = w[1], c = w[2], d = w[3];
    float p0, p1, p2, p3;
    if (*is_train != 0) {
        float m = fmaxf(fmaxf(a, b), fmaxf(c, d));
        float ea = __expf(a - m), eb = __expf(b - m);
        float ec = __expf(c - m), ed = __expf(d - m);
        float inv = __fdividef(1.0f, ea + eb + ec + ed);
        p0 = ea * inv; p1 = eb * inv; p2 = ec * inv; p3 = ed * inv;
    } else {
        int k = 0; float best = a;
        if (b > best) { best = b; k = 1; }
        if (c > best) { best = c; k = 2; }
        if (d > best) { best = d; k = 3; }
        p0 = (k == 0) ? 1.0f : 0.0f;
        p1 = (k == 1) ? 1.0f : 0.0f;
        p2 = (k == 2) ? 1.0f : 0.0f;
        p3 = (k == 3) ? 1.0f : 0.0f;
    }
    *(float4*)(g_probs + t * 4) = make_float4(p0, p1, p2, p3);
}

// Dual-row neuron, fully half2 inner loop:
//   coein rational:  N'=hfma2(b,D,N), D'=hfma2(b,N,D).
//   ein via De Morgan on complements u=1-b: same recurrence; ein=(Da-Na)/Da.
//   min/max via HMNMX2. Epilogue (mix + single reciprocal per row) in fp32.
__device__ __forceinline__ float2 neuron2(const __half2* __restrict__ bufIn, int sIn, int rp,
                                          const int* __restrict__ idxp,
                                          const float* __restrict__ probp) {
    int4 i0 = __ldg((const int4*)idxp);
    int4 i1 = __ldg(((const int4*)idxp) + 1);
    float4 p = __ldg((const float4*)probp);

    __half2 h0 = bufIn[i0.x * sIn + rp];
    __half2 h1 = bufIn[i0.y * sIn + rp];
    __half2 h2 = bufIn[i0.z * sIn + rp];
    __half2 h3 = bufIn[i0.w * sIn + rp];
    __half2 h4 = bufIn[i1.x * sIn + rp];
    __half2 h5 = bufIn[i1.y * sIn + rp];
    __half2 h6 = bufIn[i1.z * sIn + rp];
    __half2 h7 = bufIn[i1.w * sIn + rp];

    const __half2 kOne = __floats2half2_rn(1.0f, 1.0f);

    __half2 mnh = h0, mxh = h0;
    __half2 Na2 = __hsub2(kOne, h0), Da2 = kOne;   // ein (on complements)
    __half2 Nc2 = h0,                Dc2 = kOne;   // coein

#define DDLG_STEP(hv)                                   \
    {                                                   \
        mnh = __hmin2(mnh, hv);                         \
        mxh = __hmax2(mxh, hv);                         \
        __half2 u_ = __hsub2(kOne, hv);                 \
        __half2 nNa = __hfma2(u_, Da2, Na2);            \
        Da2 = __hfma2(u_, Na2, Da2);                    \
        Na2 = nNa;                                      \
        __half2 nNc = __hfma2(hv, Dc2, Nc2);            \
        Dc2 = __hfma2(hv, Nc2, Dc2);                    \
        Nc2 = nNc;                                      \
    }

    DDLG_STEP(h1) DDLG_STEP(h2) DDLG_STEP(h3) DDLG_STEP(h4)
    DDLG_STEP(h5) DDLG_STEP(h6) DDLG_STEP(h7)
#undef DDLG_STEP

    __half2 e2 = __hsub2(Da2, Na2);  // ein numerator (half precision)

    float2 mnf = __half22float2(mnh);
    float2 mxf = __half22float2(mxh);
    float2 ef  = __half22float2(e2);
    float2 Daf = __half22float2(Da2);
    float2 Ncf = __half22float2(Nc2);
    float2 Dcf = __half22float2(Dc2);

    float num0 = fmaf(p.z * ef.x, Dcf.x, (p.w * Ncf.x) * Daf.x);
    float r0 = fmaf(p.x, mnf.x, fmaf(p.y, mxf.x, __fdividef(num0, Daf.x * Dcf.x)));
    float num1 = fmaf(p.z * ef.y, Dcf.y, (p.w * Ncf.y) * Daf.y);
    float r1 = fmaf(p.x, mnf.y, fmaf(p.y, mxf.y, __fdividef(num1, Daf.y * Dcf.y)));
    return make_float2(r0, r1);
}

// Warp layout: lane = g*4 + rp  (rp = row-pair 0..3, g = neuron subgroup 0..7).
__device__ __forceinline__ void layer2(const __half2* __restrict__ bufIn, int sIn,
                                       __half2* __restrict__ bufOut, int sOut,
                                       const int* __restrict__ idx,
                                       const float* __restrict__ probs, int O) {
    int lane = threadIdx.x & 31;
    int warp = threadIdx.x >> 5;
    int rp = lane & 3;
    int g = lane >> 2;
    const int stride = NWARP * 8;  // neurons per block-iteration
    for (int o = warp * 8 + g; o < O; o += stride) {
        float2 r = neuron2(bufIn, sIn, rp, idx + o * 8, probs + o * 4);
        bufOut[o * sOut + rp] = __floats2half2_rn(r.x, r.y);
    }
}

__global__ void __launch_bounds__(THREADS, 2)
ddlg_kernel(const float* __restrict__ x,
            const int* __restrict__ idx0, const int* __restrict__ idx1,
            const int* __restrict__ idx2, const int* __restrict__ idx3,
            float* __restrict__ out) {
    extern __shared__ __half2 sm2[];
    __half2* bufA = sm2;               // stride S2A, up to 4096 cols
    __half2* bufB = sm2 + BUFA_H2;     // stride S2B, up to 2048 cols

    const int rowBase = blockIdx.x * RPB;
    const int lane = threadIdx.x & 31;
    const int warp = threadIdx.x >> 5;

    // Load 8 rows of x, transpose into row-pair half2 layout.
    // lane = rpl*8 + cc: loads float4 chunks of rows 2*rpl, 2*rpl+1.
    {
        int rpl = lane >> 3;
        int cc = lane & 7;
        const float4* xs = (const float4*)(x + (size_t)rowBase * F0);
        for (int c4 = warp * 8 + cc; c4 < F0 / 4; c4 += NWARP * 8) {
            float4 a = xs[(2 * rpl) * (F0 / 4) + c4];
            float4 b = xs[(2 * rpl + 1) * (F0 / 4) + c4];
            int c = c4 * 4;
            bufA[(c + 0) * S2A + rpl] = __floats2half2_rn(a.x, b.x);
            bufA[(c + 1) * S2A + rpl] = __floats2half2_rn(a.y, b.y);
            bufA[(c + 2) * S2A + rpl] = __floats2half2_rn(a.z, b.z);
            bufA[(c + 3) * S2A + rpl] = __floats2half2_rn(a.w, b.w);
        }
    }
    __syncthreads();

    layer2(bufA, S2A, bufB, S2B, idx0, g_probs, O0);
    __syncthreads();
    layer2(bufB, S2B, bufA, S2A, idx1, g_probs + O0 * 4, O1);
    __syncthreads();
    layer2(bufA, S2A, bufB, S2B, idx2, g_probs + (O0 + O1) * 4, O2);
    __syncthreads();
    layer2(bufB, S2B, bufA, S2A, idx3, g_probs + (O0 + O1 + O2) * 4, O3);
    __syncthreads();

    // Final store: un-pair bufA (4096 cols) into coalesced fp32 rows.
    {
        int rpl = lane >> 3;
        int cc = lane & 7;
        float4* od = (float4*)(out + (size_t)rowBase * O3);
        for (int c4 = warp * 8 + cc; c4 < O3 / 4; c4 += NWARP * 8) {
            int c = c4 * 4;
            float2 v0 = __half22float2(bufA[(c + 0) * S2A + rpl]);
            float2 v1 = __half22float2(bufA[(c + 1) * S2A + rpl]);
            float2 v2 = __half22float2(bufA[(c + 2) * S2A + rpl]);
            float2 v3 = __half22float2(bufA[(c + 3) * S2A + rpl]);
            od[(2 * rpl) * (O3 / 4) + c4]     = make_float4(v0.x, v1.x, v2.x, v3.x);
            od[(2 * rpl + 1) * (O3 / 4) + c4] = make_float4(v0.y, v1.y, v2.y, v3.y);
        }
    }
}

extern "C" void kernel_launch(void* const* d_in, const int* in_sizes, int n_in,
                              void* d_out, int out_size) {
    const float* x   = (const float*)d_in[0];
    const float* w0  = (const float*)d_in[1];
    const float* w1  = (const float*)d_in[2];
    const float* w2  = (const float*)d_in[3];
    const float* w3  = (const float*)d_in[4];
    const int* idx0  = (const int*)d_in[5];
    const int* idx1  = (const int*)d_in[6];
    const int* idx2  = (const int*)d_in[7];
    const int* idx3  = (const int*)d_in[8];
    const int* is_tr = (const int*)d_in[9];
    float* out = (float*)d_out;

    cudaFuncSetAttribute(ddlg_kernel, cudaFuncAttributeMaxDynamicSharedMemorySize, SMEM_BYTES);

    prob_kernel<<<(TOTAL_O + 255) / 256, 256>>>(w0, w1, w2, w3, is_tr);
    ddlg_kernel<<<BATCH / RPB, THREADS, SMEM_BYTES>>>(x, idx0, idx1, idx2, idx3, out);
}

// round 8
// speedup vs baseline: 1.3201x; 1.3201x over previous
#include <cuda_runtime.h>
#include <cuda_fp16.h>

// DDLG autoencoder, fully fused. Activations stored in SMEM as half2 packing
// TWO batch rows per 32-bit word; rational recurrences in fp32 (4 independent
// chains/lane for ILP), min/max in half2. Epilogue mix in fp32.
// sizes: 4096 -> 2048 -> 1024 -> 2048 -> 4096, batch 4096, NUM_CONN=8.

#define BATCH 4096
#define F0 4096
#define O0 2048
#define O1 1024
#define O2 2048
#define O3 4096
#define TOTAL_O (O0 + O1 + O2 + O3)

#define RPB 8            // batch rows per block (= 4 row-pairs)
#define THREADS 704      // 22 warps; 2 blocks * 704 * 46 regs = 64768 <= 64K RF
#define NWARP (THREADS / 32)
#define S2A 4            // half2 stride per column, buffer A (16B/col)
#define S2B 5            // half2 stride per column, buffer B (20B/col, bank-spread)
#define BUFA_H2 (F0 * S2A)   // 16384 half2 = 64KB
#define BUFB_H2 (O0 * S2B)   // 10240 half2 = 40KB
#define SMEM_BYTES ((BUFA_H2 + BUFB_H2) * 4)   // 104KB -> 2 blocks/SM

// per-neuron mixing probabilities (softmax(w) or one-hot), precomputed
__device__ float g_probs[TOTAL_O * 4];

__global__ void prob_kernel(const float* __restrict__ w0, const float* __restrict__ w1,
                            const float* __restrict__ w2, const float* __restrict__ w3,
                            const int* __restrict__ is_train) {
    int t = blockIdx.x * blockDim.x + threadIdx.x;
    if (t >= TOTAL_O) return;
    const float* w;
    if (t < O0)                w = w0 + t * 4;
    else if (t < O0 + O1)      w = w1 + (t - O0) * 4;
    else if (t < O0 + O1 + O2) w = w2 + (t - O0 - O1) * 4;
    else                       w = w3 + (t - O0 - O1 - O2) * 4;
    float a = w[0], b = w[1], c = w[2], d = w[3];
    float p0, p1, p2, p3;
    if (*is_train != 0) {
        float m = fmaxf(fmaxf(a, b), fmaxf(c, d));
        float ea = __expf(a - m), eb = __expf(b - m);
        float ec = __expf(c - m), ed = __expf(d - m);
        float inv = __fdividef(1.0f, ea + eb + ec + ed);
        p0 = ea * inv; p1 = eb * inv; p2 = ec * inv; p3 = ed * inv;
    } else {
        int k = 0; float best = a;
        if (b > best) { best = b; k = 1; }
        if (c > best) { best = c; k = 2; }
        if (d > best) { best = d; k = 3; }
        p0 = (k == 0) ? 1.0f : 0.0f;
        p1 = (k == 1) ? 1.0f : 0.0f;
        p2 = (k == 2) ? 1.0f : 0.0f;
        p3 = (k == 3) ? 1.0f : 0.0f;
    }
    *(float4*)(g_probs + t * 4) = make_float4(p0, p1, p2, p3);
}

// Dual-row neuron: one lane computes neuron o for two batch rows (packed half2).
// coein fold as rational:  N'=fma(b,D,N), D'=fma(b,N,D).
// ein via De Morgan: ein(f...) = 1 - coein(1-f...); ein = (Da-Na)/Da.
// min/max folded in half2 SIMD (exact). Single reciprocal per row at the end.
__device__ __forceinline__ float2 neuron2(const __half2* __restrict__ bufIn, int sIn, int rp,
                                          const int* __restrict__ idxp,
                                          const float* __restrict__ probp) {
    int4 i0 = __ldg((const int4*)idxp);
    int4 i1 = __ldg(((const int4*)idxp) + 1);
    float4 p = __ldg((const float4*)probp);

    __half2 h0 = bufIn[i0.x * sIn + rp];
    __half2 h1 = bufIn[i0.y * sIn + rp];
    __half2 h2 = bufIn[i0.z * sIn + rp];
    __half2 h3 = bufIn[i0.w * sIn + rp];
    __half2 h4 = bufIn[i1.x * sIn + rp];
    __half2 h5 = bufIn[i1.y * sIn + rp];
    __half2 h6 = bufIn[i1.z * sIn + rp];
    __half2 h7 = bufIn[i1.w * sIn + rp];

    __half2 mnh = h0, mxh = h0;
    float2 f = __half22float2(h0);
    float Na0 = 1.0f - f.x, Da0 = 1.0f, Nc0 = f.x, Dc0 = 1.0f;
    float Na1 = 1.0f - f.y, Da1 = 1.0f, Nc1 = f.y, Dc1 = 1.0f;

#define DDLG_STEP(hv)                                       \
    {                                                       \
        mnh = __hmin2(mnh, hv);                             \
        mxh = __hmax2(mxh, hv);                             \
        float2 fe = __half22float2(hv);                     \
        {                                                   \
            float b_ = fe.x;                                \
            float u_ = 1.0f - b_;                           \
            float nNa = fmaf(u_, Da0, Na0);                 \
            Da0 = fmaf(u_, Na0, Da0);                       \
            Na0 = nNa;                                      \
            float nNc = fmaf(b_, Dc0, Nc0);                 \
            Dc0 = fmaf(b_, Nc0, Dc0);                       \
            Nc0 = nNc;                                      \
        }                                                   \
        {                                                   \
            float b_ = fe.y;                                \
            float u_ = 1.0f - b_;                           \
            float nNa = fmaf(u_, Da1, Na1);                 \
            Da1 = fmaf(u_, Na1, Da1);                       \
            Na1 = nNa;                                      \
            float nNc = fmaf(b_, Dc1, Nc1);                 \
            Dc1 = fmaf(b_, Nc1, Dc1);                       \
            Nc1 = nNc;                                      \
        }                                                   \
    }

    DDLG_STEP(h1) DDLG_STEP(h2) DDLG_STEP(h3) DDLG_STEP(h4)
    DDLG_STEP(h5) DDLG_STEP(h6) DDLG_STEP(h7)
#undef DDLG_STEP

    float2 mnf = __half22float2(mnh);
    float2 mxf = __half22float2(mxh);

    float e0 = Da0 - Na0;
    float num0 = fmaf(p.z * e0, Dc0, (p.w * Nc0) * Da0);
    float r0 = fmaf(p.x, mnf.x, fmaf(p.y, mxf.x, __fdividef(num0, Da0 * Dc0)));
    float e1 = Da1 - Na1;
    float num1 = fmaf(p.z * e1, Dc1, (p.w * Nc1) * Da1);
    float r1 = fmaf(p.x, mnf.y, fmaf(p.y, mxf.y, __fdividef(num1, Da1 * Dc1)));
    return make_float2(r0, r1);
}

// Warp layout: lane = g*4 + rp  (rp = row-pair 0..3, g = neuron subgroup 0..7).
__device__ __forceinline__ void layer2(const __half2* __restrict__ bufIn, int sIn,
                                       __half2* __restrict__ bufOut, int sOut,
                                       const int* __restrict__ idx,
                                       const float* __restrict__ probs, int O) {
    int lane = threadIdx.x & 31;
    int warp = threadIdx.x >> 5;
    int rp = lane & 3;
    int g = lane >> 2;
    const int stride = NWARP * 8;  // neurons per block-iteration
    for (int o = warp * 8 + g; o < O; o += stride) {
        float2 r = neuron2(bufIn, sIn, rp, idx + o * 8, probs + o * 4);
        bufOut[o * sOut + rp] = __floats2half2_rn(r.x, r.y);
    }
}

__global__ void __launch_bounds__(THREADS, 2)
ddlg_kernel(const float* __restrict__ x,
            const int* __restrict__ idx0, const int* __restrict__ idx1,
            const int* __restrict__ idx2, const int* __restrict__ idx3,
            float* __restrict__ out) {
    extern __shared__ __half2 sm2[];
    __half2* bufA = sm2;               // stride S2A, up to 4096 cols
    __half2* bufB = sm2 + BUFA_H2;     // stride S2B, up to 2048 cols

    const int rowBase = blockIdx.x * RPB;
    const int lane = threadIdx.x & 31;
    const int warp = threadIdx.x >> 5;

    // Load 8 rows of x, transpose into row-pair half2 layout.
    // lane = rpl*8 + cc: loads float4 chunks of rows 2*rpl, 2*rpl+1.
    {
        int rpl = lane >> 3;
        int cc = lane & 7;
        const float4* xs = (const float4*)(x + (size_t)rowBase * F0);
        for (int c4 = warp * 8 + cc; c4 < F0 / 4; c4 += NWARP * 8) {
            float4 a = xs[(2 * rpl) * (F0 / 4) + c4];
            float4 b = xs[(2 * rpl + 1) * (F0 / 4) + c4];
            int c = c4 * 4;
            bufA[(c + 0) * S2A + rpl] = __floats2half2_rn(a.x, b.x);
            bufA[(c + 1) * S2A + rpl] = __floats2half2_rn(a.y, b.y);
            bufA[(c + 2) * S2A + rpl] = __floats2half2_rn(a.z, b.z);
            bufA[(c + 3) * S2A + rpl] = __floats2half2_rn(a.w, b.w);
        }
    }
    __syncthreads();

    layer2(bufA, S2A, bufB, S2B, idx0, g_probs, O0);
    __syncthreads();
    layer2(bufB, S2B, bufA, S2A, idx1, g_probs + O0 * 4, O1);
    __syncthreads();
    layer2(bufA, S2A, bufB, S2B, idx2, g_probs + (O0 + O1) * 4, O2);
    __syncthreads();
    layer2(bufB, S2B, bufA, S2A, idx3, g_probs + (O0 + O1 + O2) * 4, O3);
    __syncthreads();

    // Final store: un-pair bufA (4096 cols) into coalesced fp32 rows.
    {
        int rpl = lane >> 3;
        int cc = lane & 7;
        float4* od = (float4*)(out + (size_t)rowBase * O3);
        for (int c4 = warp * 8 + cc; c4 < O3 / 4; c4 += NWARP * 8) {
            int c = c4 * 4;
            float2 v0 = __half22float2(bufA[(c + 0) * S2A + rpl]);
            float2 v1 = __half22float2(bufA[(c + 1) * S2A + rpl]);
            float2 v2 = __half22float2(bufA[(c + 2) * S2A + rpl]);
            float2 v3 = __half22float2(bufA[(c + 3) * S2A + rpl]);
            od[(2 * rpl) * (O3 / 4) + c4]     = make_float4(v0.x, v1.x, v2.x, v3.x);
            od[(2 * rpl + 1) * (O3 / 4) + c4] = make_float4(v0.y, v1.y, v2.y, v3.y);
        }
    }
}

extern "C" void kernel_launch(void* const* d_in, const int* in_sizes, int n_in,
                              void* d_out, int out_size) {
    const float* x   = (const float*)d_in[0];
    const float* w0  = (const float*)d_in[1];
    const float* w1  = (const float*)d_in[2];
    const float* w2  = (const float*)d_in[3];
    const float* w3  = (const float*)d_in[4];
    const int* idx0  = (const int*)d_in[5];
    const int* idx1  = (const int*)d_in[6];
    const int* idx2  = (const int*)d_in[7];
    const int* idx3  = (const int*)d_in[8];
    const int* is_tr = (const int*)d_in[9];
    float* out = (float*)d_out;

    cudaFuncSetAttribute(ddlg_kernel, cudaFuncAttributeMaxDynamicSharedMemorySize, SMEM_BYTES);

    prob_kernel<<<(TOTAL_O + 255) / 256, 256>>>(w0, w1, w2, w3, is_tr);
    ddlg_kernel<<<BATCH / RPB, THREADS, SMEM_BYTES>>>(x, idx0, idx1, idx2, idx3, out);
}

// round 9
// speedup vs baseline: 1.3562x; 1.0273x over previous
#include <cuda_runtime.h>
#include <cuda_fp16.h>

// DDLG autoencoder, fully fused. Activations stored in SMEM as half2 packing
// TWO batch rows per 32-bit word, rp-major layout with ODD row stride
// (unaligned bank runs -> fewer LDS conflicts). Rational recurrences in fp32
// (8 independent chains/lane for ILP), min/max in half2, idx LDG prefetched
// one iteration ahead. sizes: 4096 -> 2048 -> 1024 -> 2048 -> 4096.

#define BATCH 4096
#define F0 4096
#define O0 2048
#define O1 1024
#define O2 2048
#define O3 4096
#define TOTAL_O (O0 + O1 + O2 + O3)

#define RPB 8            // batch rows per block (= 4 row-pairs)
#define THREADS 640
#define NWARP (THREADS / 32)
#define SA2 4097         // half2 row stride, buffer A (odd)
#define SB2 2049         // half2 row stride, buffer B (odd)
#define BUFA_H2 (4 * SA2)    // 16388 half2
#define BUFB_H2 (4 * SB2)    // 8196 half2
#define SMEM_BYTES ((BUFA_H2 + BUFB_H2) * 4)   // ~96KB -> 2 blocks/SM

// per-neuron mixing probabilities (softmax(w) or one-hot), precomputed
__device__ float g_probs[TOTAL_O * 4];

__global__ void prob_kernel(const float* __restrict__ w0, const float* __restrict__ w1,
                            const float* __restrict__ w2, const float* __restrict__ w3,
                            const int* __restrict__ is_train) {
    int t = blockIdx.x * blockDim.x + threadIdx.x;
    if (t >= TOTAL_O) return;
    const float* w;
    if (t < O0)                w = w0 + t * 4;
    else if (t < O0 + O1)      w = w1 + (t - O0) * 4;
    else if (t < O0 + O1 + O2) w = w2 + (t - O0 - O1) * 4;
    else                       w = w3 + (t - O0 - O1 - O2) * 4;
    float a = w[0], b = w[1], c = w[2], d = w[3];
    float p0, p1, p2, p3;
    if (*is_train != 0) {
        float m = fmaxf(fmaxf(a, b), fmaxf(c, d));
        float ea = __expf(a - m), eb = __expf(b - m);
        float ec = __expf(c - m), ed = __expf(d - m);
        float inv = __fdividef(1.0f, ea + eb + ec + ed);
        p0 = ea * inv; p1 = eb * inv; p2 = ec * inv; p3 = ed * inv;
    } else {
        int k = 0; float best = a;
        if (b > best) { best = b; k = 1; }
        if (c > best) { best = c; k = 2; }
        if (d > best) { best = d; k = 3; }
        p0 = (k == 0) ? 1.0f : 0.0f;
        p1 = (k == 1) ? 1.0f : 0.0f;
        p2 = (k == 2) ? 1.0f : 0.0f;
        p3 = (k == 3) ? 1.0f : 0.0f;
    }
    *(float4*)(g_probs + t * 4) = make_float4(p0, p1, p2, p3);
}

// Dual-row neuron body given already-loaded indices.
// coein fold as rational:  N'=fma(b,D,N), D'=fma(b,N,D).
// ein via De Morgan: ein(f...) = 1 - coein(1-f...); ein = (Da-Na)/Da.
// min/max folded in half2 SIMD (exact). Single reciprocal per row at the end.
__device__ __forceinline__ float2 neuron2_body(const __half2* __restrict__ rowIn,
                                               int4 i0, int4 i1, float4 p) {
    __half2 h0 = rowIn[i0.x];
    __half2 h1 = rowIn[i0.y];
    __half2 h2 = rowIn[i0.z];
    __half2 h3 = rowIn[i0.w];
    __half2 h4 = rowIn[i1.x];
    __half2 h5 = rowIn[i1.y];
    __half2 h6 = rowIn[i1.z];
    __half2 h7 = rowIn[i1.w];

    __half2 mnh = h0, mxh = h0;
    float2 f = __half22float2(h0);
    float Na0 = 1.0f - f.x, Da0 = 1.0f, Nc0 = f.x, Dc0 = 1.0f;
    float Na1 = 1.0f - f.y, Da1 = 1.0f, Nc1 = f.y, Dc1 = 1.0f;

#define DDLG_STEP(hv)                                       \
    {                                                       \
        mnh = __hmin2(mnh, hv);                             \
        mxh = __hmax2(mxh, hv);                             \
        float2 fe = __half22float2(hv);                     \
        {                                                   \
            float b_ = fe.x;                                \
            float u_ = 1.0f - b_;                           \
            float nNa = fmaf(u_, Da0, Na0);                 \
            Da0 = fmaf(u_, Na0, Da0);                       \
            Na0 = nNa;                                      \
            float nNc = fmaf(b_, Dc0, Nc0);                 \
            Dc0 = fmaf(b_, Nc0, Dc0);                       \
            Nc0 = nNc;                                      \
        }                                                   \
        {                                                   \
            float b_ = fe.y;                                \
            float u_ = 1.0f - b_;                           \
            float nNa = fmaf(u_, Da1, Na1);                 \
            Da1 = fmaf(u_, Na1, Da1);                       \
            Na1 = nNa;                                      \
            float nNc = fmaf(b_, Dc1, Nc1);                 \
            Dc1 = fmaf(b_, Nc1, Dc1);                       \
            Nc1 = nNc;                                      \
        }                                                   \
    }

    DDLG_STEP(h1) DDLG_STEP(h2) DDLG_STEP(h3) DDLG_STEP(h4)
    DDLG_STEP(h5) DDLG_STEP(h6) DDLG_STEP(h7)
#undef DDLG_STEP

    float2 mnf = __half22float2(mnh);
    float2 mxf = __half22float2(mxh);

    float e0 = Da0 - Na0;
    float num0 = fmaf(p.z * e0, Dc0, (p.w * Nc0) * Da0);
    float r0 = fmaf(p.x, mnf.x, fmaf(p.y, mxf.x, __fdividef(num0, Da0 * Dc0)));
    float e1 = Da1 - Na1;
    float num1 = fmaf(p.z * e1, Dc1, (p.w * Nc1) * Da1);
    float r1 = fmaf(p.x, mnf.y, fmaf(p.y, mxf.y, __fdividef(num1, Da1 * Dc1)));
    return make_float2(r0, r1);
}

// Warp layout: lane = g*4 + rp  (rp = row-pair 0..3, g = neuron subgroup 0..7).
// rp-major buffers: element (col, rp) at buf[rp * sRow + col].
// idx for the NEXT iteration is prefetched while the current one computes.
__device__ __forceinline__ void layer2(const __half2* __restrict__ bufIn, int sIn,
                                       __half2* __restrict__ bufOut, int sOut,
                                       const int* __restrict__ idx,
                                       const float* __restrict__ probs, int O) {
    int lane = threadIdx.x & 31;
    int warp = threadIdx.x >> 5;
    int rp = lane & 3;
    int g = lane >> 2;
    const __half2* rowIn = bufIn + rp * sIn;
    __half2* rowOut = bufOut + rp * sOut;
    const int stride = NWARP * 8;  // neurons per block-iteration

    int o = warp * 8 + g;
    if (o >= O) return;
    int4 ia = __ldg((const int4*)(idx + o * 8));
    int4 ib = __ldg((const int4*)(idx + o * 8) + 1);
    while (true) {
        int on = o + stride;
        int4 na, nb;
        if (on < O) {
            na = __ldg((const int4*)(idx + on * 8));
            nb = __ldg((const int4*)(idx + on * 8) + 1);
        }
        float4 p = __ldg((const float4*)(probs + o * 4));
        float2 r = neuron2_body(rowIn, ia, ib, p);
        rowOut[o] = __floats2half2_rn(r.x, r.y);
        if (on >= O) break;
        o = on; ia = na; ib = nb;
    }
}

__global__ void __launch_bounds__(THREADS, 2)
ddlg_kernel(const float* __restrict__ x,
            const int* __restrict__ idx0, const int* __restrict__ idx1,
            const int* __restrict__ idx2, const int* __restrict__ idx3,
            float* __restrict__ out) {
    extern __shared__ __half2 sm2[];
    __half2* bufA = sm2;               // rp-major, stride SA2, up to 4096 cols
    __half2* bufB = sm2 + BUFA_H2;     // rp-major, stride SB2, up to 2048 cols

    const int rowBase = blockIdx.x * RPB;
    const int lane = threadIdx.x & 31;
    const int warp = threadIdx.x >> 5;

    // Load 8 rows of x, transpose into rp-major half2 layout.
    // lane = rpl*8 + cc: loads float4 chunks of rows 2*rpl, 2*rpl+1.
    // Writes 4 consecutive half2 (16B) per lane -> conflict-free.
    {
        int rpl = lane >> 3;
        int cc = lane & 7;
        const float4* xs = (const float4*)(x + (size_t)rowBase * F0);
        for (int c4 = warp * 8 + cc; c4 < F0 / 4; c4 += NWARP * 8) {
            float4 a = xs[(2 * rpl) * (F0 / 4) + c4];
            float4 b = xs[(2 * rpl + 1) * (F0 / 4) + c4];
            int c = c4 * 4;
            __half2* d = bufA + rpl * SA2 + c;
            d[0] = __floats2half2_rn(a.x, b.x);
            d[1] = __floats2half2_rn(a.y, b.y);
            d[2] = __floats2half2_rn(a.z, b.z);
            d[3] = __floats2half2_rn(a.w, b.w);
        }
    }
    __syncthreads();

    layer2(bufA, SA2, bufB, SB2, idx0, g_probs, O0);
    __syncthreads();
    layer2(bufB, SB2, bufA, SA2, idx1, g_probs + O0 * 4, O1);
    __syncthreads();
    layer2(bufA, SA2, bufB, SB2, idx2, g_probs + (O0 + O1) * 4, O2);
    __syncthreads();
    layer2(bufB, SB2, bufA, SA2, idx3, g_probs + (O0 + O1 + O2) * 4, O3);
    __syncthreads();

    // Final store: un-pair bufA (4096 cols) into coalesced fp32 rows.
    {
        int rpl = lane >> 3;
        int cc = lane & 7;
        float4* od = (float4*)(out + (size_t)rowBase * O3);
        for (int c4 = warp * 8 + cc; c4 < O3 / 4; c4 += NWARP * 8) {
            int c = c4 * 4;
            const __half2* s = bufA + rpl * SA2 + c;
            float2 v0 = __half22float2(s[0]);
            float2 v1 = __half22float2(s[1]);
            float2 v2 = __half22float2(s[2]);
            float2 v3 = __half22float2(s[3]);
            od[(2 * rpl) * (O3 / 4) + c4]     = make_float4(v0.x, v1.x, v2.x, v3.x);
            od[(2 * rpl + 1) * (O3 / 4) + c4] = make_float4(v0.y, v1.y, v2.y, v3.y);
        }
    }
}

extern "C" void kernel_launch(void* const* d_in, const int* in_sizes, int n_in,
                              void* d_out, int out_size) {
    const float* x   = (const float*)d_in[0];
    const float* w0  = (const float*)d_in[1];
    const float* w1  = (const float*)d_in[2];
    const float* w2  = (const float*)d_in[3];
    const float* w3  = (const float*)d_in[4];
    const int* idx0  = (const int*)d_in[5];
    const int* idx1  = (const int*)d_in[6];
    const int* idx2  = (const int*)d_in[7];
    const int* idx3  = (const int*)d_in[8];
    const int* is_tr = (const int*)d_in[9];
    float* out = (float*)d_out;

    cudaFuncSetAttribute(ddlg_kernel, cudaFuncAttributeMaxDynamicSharedMemorySize, SMEM_BYTES);

    prob_kernel<<<(TOTAL_O + 255) / 256, 256>>>(w0, w1, w2, w3, is_tr);
    ddlg_kernel<<<BATCH / RPB, THREADS, SMEM_BYTES>>>(x, idx0, idx1, idx2, idx3, out);
}

// round 12
// speedup vs baseline: 1.4378x; 1.0601x over previous
#include <cuda_runtime.h>
#include <cuda_fp16.h>

// DDLG autoencoder, fully fused. Activations in SMEM as half2 (2 batch rows
// per 32-bit word), col-major layout: element (col, rp) at buf[col*stride + rp].
// One lane owns ONE neuron x FOUR rows (2 row-pairs) -> 8-byte LDS.64 gathers.
// Rational gate recurrences in fp32 (8 independent chains/lane), min/max half2.
// sizes: 4096 -> 2048 -> 1024 -> 2048 -> 4096, batch 4096, NUM_CONN=8.

#define BATCH 4096
#define F0 4096
#define O0 2048
#define O1 1024
#define O2 2048
#define O3 4096
#define TOTAL_O (O0 + O1 + O2 + O3)

#define RPB 8            // batch rows per block (= 4 row-pairs = 2 quads)
#define THREADS 640
#define NWARP (THREADS / 32)
#define SA2 4            // half2 stride per column, buffer A (16B/col)
#define SB2 6            // half2 stride per column, buffer B (24B/col, even->8B aligned)
#define BUFA_H2 (F0 * SA2)   // 16384 half2 = 64KB
#define BUFB_H2 (O0 * SB2)   // 12288 half2 = 48KB
#define SMEM_BYTES ((BUFA_H2 + BUFB_H2) * 4)   // 112KB -> 2 blocks/SM

// per-neuron mixing probabilities (softmax(w) or one-hot), precomputed
__device__ float g_probs[TOTAL_O * 4];

__global__ void prob_kernel(const float* __restrict__ w0, const float* __restrict__ w1,
                            const float* __restrict__ w2, const float* __restrict__ w3,
                            const int* __restrict__ is_train) {
    int t = blockIdx.x * blockDim.x + threadIdx.x;
    if (t >= TOTAL_O) return;
    const float* w;
    if (t < O0)                w = w0 + t * 4;
    else if (t < O0 + O1)      w = w1 + (t - O0) * 4;
    else if (t < O0 + O1 + O2) w = w2 + (t - O0 - O1) * 4;
    else                       w = w3 + (t - O0 - O1 - O2) * 4;
    float a = w[0], b = w[1], c = w[2], d = w[3];
    float p0, p1, p2, p3;
    if (*is_train != 0) {
        float m = fmaxf(fmaxf(a, b), fmaxf(c, d));
        float ea = __expf(a - m), eb = __expf(b - m);
        float ec = __expf(c - m), ed = __expf(d - m);
        float inv = __fdividef(1.0f, ea + eb + ec + ed);
        p0 = ea * inv; p1 = eb * inv; p2 = ec * inv; p3 = ed * inv;
    } else {
        int k = 0; float best = a;
        if (b > best) { best = b; k = 1; }
        if (c > best) { best = c; k = 2; }
        if (d > best) { best = d; k = 3; }
        p0 = (k == 0) ? 1.0f : 0.0f;
        p1 = (k == 1) ? 1.0f : 0.0f;
        p2 = (k == 2) ? 1.0f : 0.0f;
        p3 = (k == 3) ? 1.0f : 0.0f;
    }
    *(float4*)(g_probs + t * 4) = make_float4(p0, p1, p2, p3);
}

// One neuron x 4 rows. Gathers are LDS.64 (two half2 = 4 rows per connection).
// coein fold as rational:  N'=fma(b,D,N), D'=fma(b,N,D).
// ein via De Morgan: ein(f...) = 1 - coein(1-f...); ein = (Da-Na)/Da.
// min/max folded in half2 SIMD (exact). Single reciprocal per row at the end.
__device__ __forceinline__ void neuron4(const __half2* __restrict__ colBase, int sIn,
                                        const int* __restrict__ idxp,
                                        const float* __restrict__ probp,
                                        __half2* __restrict__ outp) {
    int4 i0 = __ldg((const int4*)idxp);
    int4 i1 = __ldg(((const int4*)idxp) + 1);
    float4 p = __ldg((const float4*)probp);

    uint2 w0 = *(const uint2*)(colBase + i0.x * sIn);
    uint2 w1 = *(const uint2*)(colBase + i0.y * sIn);
    uint2 w2 = *(const uint2*)(colBase + i0.z * sIn);
    uint2 w3 = *(const uint2*)(colBase + i0.w * sIn);
    uint2 w4 = *(const uint2*)(colBase + i1.x * sIn);
    uint2 w5 = *(const uint2*)(colBase + i1.y * sIn);
    uint2 w6 = *(const uint2*)(colBase + i1.z * sIn);
    uint2 w7 = *(const uint2*)(colBase + i1.w * sIn);

    __half2 lo = __halves2half2(__ushort_as_half((unsigned short)(w0.x & 0xFFFF)),
                                __ushort_as_half((unsigned short)(w0.x >> 16)));
    __half2 hi = __halves2half2(__ushort_as_half((unsigned short)(w0.y & 0xFFFF)),
                                __ushort_as_half((unsigned short)(w0.y >> 16)));
    // (the above is just a reinterpret; compiler folds it to register moves)

    __half2 mnl = lo, mxl = lo, mnh = hi, mxh = hi;
    float2 fl = __half22float2(lo);
    float2 fh = __half22float2(hi);
    float Na0 = 1.0f - fl.x, Da0 = 1.0f, Nc0 = fl.x, Dc0 = 1.0f;
    float Na1 = 1.0f - fl.y, Da1 = 1.0f, Nc1 = fl.y, Dc1 = 1.0f;
    float Na2 = 1.0f - fh.x, Da2 = 1.0f, Nc2 = fh.x, Dc2 = 1.0f;
    float Na3 = 1.0f - fh.y, Da3 = 1.0f, Nc3 = fh.y, Dc3 = 1.0f;

#define ROW_STEP(b_, Na, Da, Nc, Dc)                        \
    {                                                       \
        float u_ = 1.0f - (b_);                             \
        float nNa = fmaf(u_, Da, Na);                       \
        Da = fmaf(u_, Na, Da);                              \
        Na = nNa;                                           \
        float nNc = fmaf((b_), Dc, Nc);                     \
        Dc = fmaf((b_), Nc, Dc);                            \
        Nc = nNc;                                           \
    }

#define DDLG_STEP(wv)                                                   \
    {                                                                   \
        __half2 l_ = *(const __half2*)&(wv).x;                          \
        __half2 h_ = *(const __half2*)&(wv).y;                          \
        mnl = __hmin2(mnl, l_); mxl = __hmax2(mxl, l_);                 \
        mnh = __hmin2(mnh, h_); mxh = __hmax2(mxh, h_);                 \
        float2 fl_ = __half22float2(l_);                                \
        float2 fh_ = __half22float2(h_);                                \
        ROW_STEP(fl_.x, Na0, Da0, Nc0, Dc0)                             \
        ROW_STEP(fl_.y, Na1, Da1, Nc1, Dc1)                             \
        ROW_STEP(fh_.x, Na2, Da2, Nc2, Dc2)                             \
        ROW_STEP(fh_.y, Na3, Da3, Nc3, Dc3)                             \
    }

    DDLG_STEP(w1) DDLG_STEP(w2) DDLG_STEP(w3) DDLG_STEP(w4)
    DDLG_STEP(w5) DDLG_STEP(w6) DDLG_STEP(w7)
#undef DDLG_STEP
#undef ROW_STEP

    float2 mnlf = __half22float2(mnl), mxlf = __half22float2(mxl);
    float2 mnhf = __half22float2(mnh), mxhf = __half22float2(mxh);

    float e0 = Da0 - Na0;
    float num0 = fmaf(p.z * e0, Dc0, (p.w * Nc0) * Da0);
    float r0 = fmaf(p.x, mnlf.x, fmaf(p.y, mxlf.x, __fdividef(num0, Da0 * Dc0)));
    float e1 = Da1 - Na1;
    float num1 = fmaf(p.z * e1, Dc1, (p.w * Nc1) * Da1);
    float r1 = fmaf(p.x, mnlf.y, fmaf(p.y, mxlf.y, __fdividef(num1, Da1 * Dc1)));
    float e2 = Da2 - Na2;
    float num2 = fmaf(p.z * e2, Dc2, (p.w * Nc2) * Da2);
    float r2 = fmaf(p.x, mnhf.x, fmaf(p.y, mxhf.x, __fdividef(num2, Da2 * Dc2)));
    float e3 = Da3 - Na3;
    float num3 = fmaf(p.z * e3, Dc3, (p.w * Nc3) * Da3);
    float r3 = fmaf(p.x, mnhf.y, fmaf(p.y, mxhf.y, __fdividef(num3, Da3 * Dc3)));

    uint2 outw;
    __half2 o0 = __floats2half2_rn(r0, r1);
    __half2 o1 = __floats2half2_rn(r2, r3);
    outw.x = *(const unsigned int*)&o0;
    outw.y = *(const unsigned int*)&o1;
    *(uint2*)outp = outw;
}

// Warp layout: lane = g*2 + q  (q = row-quad 0..1, g = neuron subgroup 0..15).
__device__ __forceinline__ void layer4(const __half2* __restrict__ bufIn, int sIn,
                                       __half2* __restrict__ bufOut, int sOut,
                                       const int* __restrict__ idx,
                                       const float* __restrict__ probs, int O) {
    int lane = threadIdx.x & 31;
    int warp = threadIdx.x >> 5;
    int q = lane & 1;
    int g = lane >> 1;
    const __half2* colBase = bufIn + 2 * q;
    const int stride = NWARP * 16;  // neurons per block-iteration
    for (int o = warp * 16 + g; o < O; o += stride) {
        neuron4(colBase, sIn, idx + o * 8, probs + o * 4, bufOut + o * sOut + 2 * q);
    }
}

__global__ void __launch_bounds__(THREADS, 2)
ddlg_kernel(const float* __restrict__ x,
            const int* __restrict__ idx0, const int* __restrict__ idx1,
            const int* __restrict__ idx2, const int* __restrict__ idx3,
            float* __restrict__ out) {
    extern __shared__ __half2 sm2[];
    __half2* bufA = sm2;               // col-major stride SA2, up to 4096 cols
    __half2* bufB = sm2 + BUFA_H2;     // col-major stride SB2, up to 2048 cols

    const int rowBase = blockIdx.x * RPB;
    const int lane = threadIdx.x & 31;
    const int warp = threadIdx.x >> 5;

    // Load 8 rows of x, transpose into col-major row-pair half2 layout.
    // lane = rpl*8 + cc: loads float4 chunks of rows 2*rpl, 2*rpl+1.
    {
        int rpl = lane >> 3;
        int cc = lane & 7;
        const float4* xs = (const float4*)(x + (size_t)rowBase * F0);
        for (int c4 = warp * 8 + cc; c4 < F0 / 4; c4 += NWARP * 8) {
            float4 a = xs[(2 * rpl) * (F0 / 4) + c4];
            float4 b = xs[(2 * rpl + 1) * (F0 / 4) + c4];
            int c = c4 * 4;
            bufA[(c + 0) * SA2 + rpl] = __floats2half2_rn(a.x, b.x);
            bufA[(c + 1) * SA2 + rpl] = __floats2half2_rn(a.y, b.y);
            bufA[(c + 2) * SA2 + rpl] = __floats2half2_rn(a.z, b.z);
            bufA[(c + 3) * SA2 + rpl] = __floats2half2_rn(a.w, b.w);
        }
    }
    __syncthreads();

    layer4(bufA, SA2, bufB, SB2, idx0, g_probs, O0);
    __syncthreads();
    layer4(bufB, SB2, bufA, SA2, idx1, g_probs + O0 * 4, O1);
    __syncthreads();
    layer4(bufA, SA2, bufB, SB2, idx2, g_probs + (O0 + O1) * 4, O2);
    __syncthreads();
    layer4(bufB, SB2, bufA, SA2, idx3, g_probs + (O0 + O1 + O2) * 4, O3);
    __syncthreads();

    // Final store: un-pair bufA (4096 cols) into coalesced fp32 rows.
    {
        int rpl = lane >> 3;
        int cc = lane & 7;
        float4* od = (float4*)(out + (size_t)rowBase * O3);
        for (int c4 = warp * 8 + cc; c4 < O3 / 4; c4 += NWARP * 8) {
            int c = c4 * 4;
            float2 v0 = __half22float2(bufA[(c + 0) * SA2 + rpl]);
            float2 v1 = __half22float2(bufA[(c + 1) * SA2 + rpl]);
            float2 v2 = __half22float2(bufA[(c + 2) * SA2 + rpl]);
            float2 v3 = __half22float2(bufA[(c + 3) * SA2 + rpl]);
            od[(2 * rpl) * (O3 / 4) + c4]     = make_float4(v0.x, v1.x, v2.x, v3.x);
            od[(2 * rpl + 1) * (O3 / 4) + c4] = make_float4(v0.y, v1.y, v2.y, v3.y);
        }
    }
}

extern "C" void kernel_launch(void* const* d_in, const int* in_sizes, int n_in,
                              void* d_out, int out_size) {
    const float* x   = (const float*)d_in[0];
    const float* w0  = (const float*)d_in[1];
    const float* w1  = (const float*)d_in[2];
    const float* w2  = (const float*)d_in[3];
    const float* w3  = (const float*)d_in[4];
    const int* idx0  = (const int*)d_in[5];
    const int* idx1  = (const int*)d_in[6];
    const int* idx2  = (const int*)d_in[7];
    const int* idx3  = (const int*)d_in[8];
    const int* is_tr = (const int*)d_in[9];
    float* out = (float*)d_out;

    cudaFuncSetAttribute(ddlg_kernel, cudaFuncAttributeMaxDynamicSharedMemorySize, SMEM_BYTES);

    prob_kernel<<<(TOTAL_O + 255) / 256, 256>>>(w0, w1, w2, w3, is_tr);
    ddlg_kernel<<<BATCH / RPB, THREADS, SMEM_BYTES>>>(x, idx0, idx1, idx2, idx3, out);
}